// round 2
// baseline (speedup 1.0000x reference)
#include <cuda_runtime.h>
#include <mma.h>
#include <math.h>
#include <stdint.h>

using namespace nvcuda;

#define Bb 2
#define Tt 2048
#define Cc 2048
#define Hh 32
#define Nn 64
#define BT (Bb*Tt)            /* 4096 */
#define NEL (Bb*Tt*Cc)        /* 8388608 */

// ---------------------------------------------------------------------------
// Scratch (device globals; no dynamic allocation allowed)
// ---------------------------------------------------------------------------
__device__ float G_XXX[NEL];
__device__ float G_L1[BT*256];      // lora1 out, padded N: 160 -> 256
__device__ float G_M5[5][NEL];      // 5 mix deltas
__device__ float G_XW[NEL];
__device__ float G_XK[NEL];
__device__ float G_XV[NEL];
__device__ float G_XR[NEL];
__device__ float G_XG[NEL];
__device__ float G_D1[BT*128];      // decay lora1 out, padded N: 64 -> 128
__device__ float G_WW[NEL];         // decay -> exp(-exp(w)) in place
__device__ float G_R[NEL];
__device__ float G_K[NEL];
__device__ float G_V[NEL];
__device__ float G_GL[NEL];
__device__ float G_WKV[NEL];
__device__ float G_OGX[NEL];

// ---------------------------------------------------------------------------
// TF32 WMMA GEMM, software-pipelined (register prefetch of next K tile).
//   C[M,N] = A[M,K] * B
//   BMODE==1 (NT): B given as W[N,K] row-major  (C = A * W^T)
//   BMODE==0 (NN): B given as B[K,N] row-major  (C = A * B)
// Batched over blockIdx.z with element strides aBatch/bBatch/cBatch.
// M is implied by gridDim.y*128 (always 4096 here). K must be multiple of 32.
// Partial N tiles handled by zero-fill on B loads; C buffers padded so full
// tile stores stay in bounds.
// ---------------------------------------------------------------------------
template<int BMODE>
__global__ __launch_bounds__(256)
void gemm_tf32(const float* __restrict__ A, int lda, size_t aBatch,
               const float* __restrict__ Bm, int ldb, size_t bBatch,
               float* __restrict__ C, int ldc, size_t cBatch,
               int Nreal, int Kdim)
{
    constexpr int BM = 128, BN = 128, BK = 32;
    constexpr int LDAS = BK + 4;       // 36
    constexpr int LDBS_NN = BN + 4;    // 132

    __shared__ __align__(16) float As[BM * LDAS];
    __shared__ __align__(16) float Bs[BMODE ? (BN * LDAS) : (BK * LDBS_NN)];

    A  += (size_t)blockIdx.z * aBatch;
    Bm += (size_t)blockIdx.z * bBatch;
    C  += (size_t)blockIdx.z * cBatch;

    const int tid = threadIdx.x;
    const int wid = tid >> 5;
    const int wm  = wid & 3;    // 4 warps along M (32 rows each)
    const int wn  = wid >> 2;   // 2 warps along N (64 cols each)
    const int m0  = blockIdx.y * BM;
    const int n0  = blockIdx.x * BN;

    // Per-thread staging coordinates (idx = tid + it*256)
    int rowA[4], kqA[4];
    int rowB[4], nqB[4];
#pragma unroll
    for (int it = 0; it < 4; it++) {
        int idx = tid + it * 256;
        rowA[it] = idx >> 3;  kqA[it] = idx & 7;          // A tile + B(NT) tile
        rowB[it] = idx >> 5;  nqB[it] = idx & 31;         // B(NN) tile
    }

    wmma::fragment<wmma::accumulator, 16, 16, 8, float> acc[2][4];
#pragma unroll
    for (int i = 0; i < 2; i++)
#pragma unroll
        for (int j = 0; j < 4; j++)
            wmma::fill_fragment(acc[i][j], 0.0f);

    float4 ra[4], rb[4];

    // ---- tile loaders (gmem -> regs) ----
    auto loadA = [&](int k0) {
#pragma unroll
        for (int it = 0; it < 4; it++)
            ra[it] = *(const float4*)(A + (size_t)(m0 + rowA[it]) * lda + k0 + kqA[it] * 4);
    };
    auto loadB = [&](int k0) {
        if (BMODE) {
#pragma unroll
            for (int it = 0; it < 4; it++) {
                rb[it] = make_float4(0.f, 0.f, 0.f, 0.f);
                if (n0 + rowA[it] < Nreal)
                    rb[it] = *(const float4*)(Bm + (size_t)(n0 + rowA[it]) * ldb + k0 + kqA[it] * 4);
            }
        } else {
#pragma unroll
            for (int it = 0; it < 4; it++) {
                rb[it] = make_float4(0.f, 0.f, 0.f, 0.f);
                if (n0 + nqB[it] * 4 < Nreal)
                    rb[it] = *(const float4*)(Bm + (size_t)(k0 + rowB[it]) * ldb + n0 + nqB[it] * 4);
            }
        }
    };
    // ---- regs -> smem ----
    auto storeTiles = [&]() {
#pragma unroll
        for (int it = 0; it < 4; it++)
            *(float4*)(As + rowA[it] * LDAS + kqA[it] * 4) = ra[it];
        if (BMODE) {
#pragma unroll
            for (int it = 0; it < 4; it++)
                *(float4*)(Bs + rowA[it] * LDAS + kqA[it] * 4) = rb[it];
        } else {
#pragma unroll
            for (int it = 0; it < 4; it++)
                *(float4*)(Bs + rowB[it] * LDBS_NN + nqB[it] * 4) = rb[it];
        }
    };
    // ---- compute one K tile from smem ----
    auto compute = [&]() {
#pragma unroll
        for (int kk = 0; kk < BK; kk += 8) {
            wmma::fragment<wmma::matrix_a, 16, 16, 8, wmma::precision::tf32, wmma::row_major> af[2];
#pragma unroll
            for (int i = 0; i < 2; i++) {
                wmma::load_matrix_sync(af[i], As + (wm * 32 + i * 16) * LDAS + kk, LDAS);
#pragma unroll
                for (int t = 0; t < af[i].num_elements; t++)
                    af[i].x[t] = wmma::__float_to_tf32(af[i].x[t]);
            }
            if (BMODE) {
#pragma unroll
                for (int j = 0; j < 4; j++) {
                    wmma::fragment<wmma::matrix_b, 16, 16, 8, wmma::precision::tf32, wmma::col_major> bf;
                    wmma::load_matrix_sync(bf, Bs + (wn * 64 + j * 16) * LDAS + kk, LDAS);
#pragma unroll
                    for (int t = 0; t < bf.num_elements; t++)
                        bf.x[t] = wmma::__float_to_tf32(bf.x[t]);
#pragma unroll
                    for (int i = 0; i < 2; i++)
                        wmma::mma_sync(acc[i][j], af[i], bf, acc[i][j]);
                }
            } else {
#pragma unroll
                for (int j = 0; j < 4; j++) {
                    wmma::fragment<wmma::matrix_b, 16, 16, 8, wmma::precision::tf32, wmma::row_major> bf;
                    wmma::load_matrix_sync(bf, Bs + kk * LDBS_NN + wn * 64 + j * 16, LDBS_NN);
#pragma unroll
                    for (int t = 0; t < bf.num_elements; t++)
                        bf.x[t] = wmma::__float_to_tf32(bf.x[t]);
#pragma unroll
                    for (int i = 0; i < 2; i++)
                        wmma::mma_sync(acc[i][j], af[i], bf, acc[i][j]);
                }
            }
        }
    };

    // ---- pipelined mainloop ----
    loadA(0); loadB(0);
    storeTiles();
    __syncthreads();

    int k0 = 0;
    while (true) {
        int knext = k0 + BK;
        bool more = knext < Kdim;
        if (more) { loadA(knext); loadB(knext); }   // prefetch overlaps MMA below
        compute();
        __syncthreads();
        if (!more) break;
        storeTiles();
        __syncthreads();
        k0 = knext;
    }

#pragma unroll
    for (int i = 0; i < 2; i++)
#pragma unroll
        for (int j = 0; j < 4; j++)
            wmma::store_matrix_sync(C + (size_t)(m0 + wm * 32 + i * 16) * ldc
                                      + n0 + wn * 64 + j * 16,
                                    acc[i][j], ldc, wmma::mem_row_major);
}

// ---------------------------------------------------------------------------
// Elementwise kernels (float4 over NEL; Cc/4 = 512, Tt = 2048 — powers of 2)
// ---------------------------------------------------------------------------
__global__ void k_xxx(const float* __restrict__ x, const float* __restrict__ maa_x)
{
    int i = blockIdx.x * blockDim.x + threadIdx.x;
    if (i >= NEL / 4) return;
    int c4 = i & 511;
    int bt = i >> 9;
    int t  = bt & (Tt - 1);
    float4 xv = ((const float4*)x)[i];
    float4 xp = make_float4(0.f, 0.f, 0.f, 0.f);
    if (t > 0) xp = ((const float4*)x)[i - 512];
    float4 mm = ((const float4*)maa_x)[c4];
    float4 o;
    o.x = xv.x + (xp.x - xv.x) * mm.x;
    o.y = xv.y + (xp.y - xv.y) * mm.y;
    o.z = xv.z + (xp.z - xv.z) * mm.z;
    o.w = xv.w + (xp.w - xv.w) * mm.w;
    ((float4*)G_XXX)[i] = o;
}

__global__ void k_tanh(float* __restrict__ p, int n)
{
    int i = blockIdx.x * blockDim.x + threadIdx.x;
    if (i < n) p[i] = tanhf(p[i]);
}

__global__ void k_mix(const float* __restrict__ x,
                      const float* __restrict__ maw, const float* __restrict__ mak,
                      const float* __restrict__ mav, const float* __restrict__ mar,
                      const float* __restrict__ mag)
{
    int i = blockIdx.x * blockDim.x + threadIdx.x;
    if (i >= NEL / 4) return;
    int c4 = i & 511;
    int bt = i >> 9;
    int t  = bt & (Tt - 1);
    float4 xv = ((const float4*)x)[i];
    float4 xp = make_float4(0.f, 0.f, 0.f, 0.f);
    if (t > 0) xp = ((const float4*)x)[i - 512];
    float4 xx;
    xx.x = xp.x - xv.x; xx.y = xp.y - xv.y; xx.z = xp.z - xv.z; xx.w = xp.w - xv.w;

#define MIX_ONE(MAA, FIDX, DST)                                              \
    {                                                                        \
        float4 ma = ((const float4*)(MAA))[c4];                              \
        float4 md = ((const float4*)(G_M5[FIDX]))[i];                        \
        float4 o;                                                            \
        o.x = xv.x + xx.x * (ma.x + md.x);                                   \
        o.y = xv.y + xx.y * (ma.y + md.y);                                   \
        o.z = xv.z + xx.z * (ma.z + md.z);                                   \
        o.w = xv.w + xx.w * (ma.w + md.w);                                   \
        ((float4*)(DST))[i] = o;                                             \
    }
    MIX_ONE(maw, 0, G_XW)
    MIX_ONE(mak, 1, G_XK)
    MIX_ONE(mav, 2, G_XV)
    MIX_ONE(mar, 3, G_XR)
    MIX_ONE(mag, 4, G_XG)
#undef MIX_ONE
}

__global__ void k_ew(const float* __restrict__ td)
{
    int i = blockIdx.x * blockDim.x + threadIdx.x;
    if (i >= NEL / 4) return;
    int c4 = i & 511;
    float4 wv = ((float4*)G_WW)[i];
    float4 tv = ((const float4*)td)[c4];
    wv.x = expf(-expf(tv.x + wv.x));
    wv.y = expf(-expf(tv.y + wv.y));
    wv.z = expf(-expf(tv.z + wv.z));
    wv.w = expf(-expf(tv.w + wv.w));
    ((float4*)G_WW)[i] = wv;
}

// ---------------------------------------------------------------------------
// WKV6 recurrence.  grid (2, H, B): vsplit, head, batch.  128 threads:
// thread = (vcol 0..31, kquarter 0..3); 16 state elements per thread.
// ---------------------------------------------------------------------------
__global__ __launch_bounds__(128)
void k_wkv(const float* __restrict__ U)
{
    __shared__ __align__(16) float sr[64];
    __shared__ __align__(16) float sk[64];
    __shared__ __align__(16) float sew[64];
    __shared__ __align__(16) float sv[32];
    __shared__ float sacc[128];

    const int tid  = threadIdx.x;
    const int vs   = blockIdx.x;          // 0/1
    const int h    = blockIdx.y;
    const int b    = blockIdx.z;
    const int vloc = tid & 31;
    const int kq   = tid >> 5;            // 0..3
    const int k0   = kq * 16;

    float u[16], s[16];
#pragma unroll
    for (int i = 0; i < 16; i++) {
        u[i] = U[h * 64 + k0 + i];
        s[i] = 0.f;
    }

    size_t base = (size_t)b * Tt * Cc + (size_t)h * 64;
    for (int t = 0; t < Tt; t++, base += Cc) {
        if (tid < 64) {
            sr[tid]  = G_R[base + tid];
            sew[tid] = G_WW[base + tid];
        } else {
            int j = tid - 64;
            sk[j] = G_K[base + j];
            if (j < 32) sv[j] = G_V[base + vs * 32 + j];
        }
        __syncthreads();

        const float vj = sv[vloc];
        float acc = 0.f;
        const float4* r4 = (const float4*)(sr + k0);
        const float4* c4 = (const float4*)(sk + k0);
        const float4* e4 = (const float4*)(sew + k0);
#pragma unroll
        for (int q = 0; q < 4; q++) {
            float4 rr = r4[q], kk = c4[q], ee = e4[q];
            float p;
            p = kk.x * vj; acc = fmaf(rr.x, fmaf(u[q*4+0], p, s[q*4+0]), acc); s[q*4+0] = fmaf(ee.x, s[q*4+0], p);
            p = kk.y * vj; acc = fmaf(rr.y, fmaf(u[q*4+1], p, s[q*4+1]), acc); s[q*4+1] = fmaf(ee.y, s[q*4+1], p);
            p = kk.z * vj; acc = fmaf(rr.z, fmaf(u[q*4+2], p, s[q*4+2]), acc); s[q*4+2] = fmaf(ee.z, s[q*4+2], p);
            p = kk.w * vj; acc = fmaf(rr.w, fmaf(u[q*4+3], p, s[q*4+3]), acc); s[q*4+3] = fmaf(ee.w, s[q*4+3], p);
        }
        sacc[tid] = acc;
        __syncthreads();
        if (tid < 32)
            G_WKV[base + vs * 32 + tid] =
                sacc[tid] + sacc[tid + 32] + sacc[tid + 64] + sacc[tid + 96];
    }
}

// ---------------------------------------------------------------------------
// GroupNorm(per head) * ln_w + ln_b, then * silu(g).  One block per token.
// ---------------------------------------------------------------------------
__global__ __launch_bounds__(256)
void k_gn(const float* __restrict__ lnw, const float* __restrict__ lnb)
{
    const int token = blockIdx.x;          // 0..4095
    const int lane  = threadIdx.x & 31;
    const int w     = threadIdx.x >> 5;    // 0..7
    const size_t tbase = (size_t)token * Cc;
#pragma unroll
    for (int hh = 0; hh < 4; hh++) {
        int h = w * 4 + hh;
        size_t base = tbase + (size_t)h * 64;
        float e0 = G_WKV[base + lane];
        float e1 = G_WKV[base + 32 + lane];
        float sum = e0 + e1;
#pragma unroll
        for (int o = 16; o > 0; o >>= 1) sum += __shfl_xor_sync(0xffffffffu, sum, o);
        float mean = sum * (1.f / 64.f);
        float d0 = e0 - mean, d1 = e1 - mean;
        float vr = d0 * d0 + d1 * d1;
#pragma unroll
        for (int o = 16; o > 0; o >>= 1) vr += __shfl_xor_sync(0xffffffffu, vr, o);
        float inv = rsqrtf(vr * (1.f / 64.f) + 6.4e-4f);   // EPS = 1e-5 * 8^2
        int c0 = h * 64 + lane, c1 = c0 + 32;
        float g0 = G_GL[base + lane];
        float g1 = G_GL[base + 32 + lane];
        g0 = g0 / (1.f + expf(-g0));
        g1 = g1 / (1.f + expf(-g1));
        G_OGX[base + lane]      = (d0 * inv * lnw[c0] + lnb[c0]) * g0;
        G_OGX[base + 32 + lane] = (d1 * inv * lnw[c1] + lnb[c1]) * g1;
    }
}

// ---------------------------------------------------------------------------
// Host launch
// ---------------------------------------------------------------------------
static float* sym_addr(const void* symbol)
{
    void* p = nullptr;
    cudaGetSymbolAddress(&p, symbol);
    return (float*)p;
}

extern "C" void kernel_launch(void* const* d_in, const int* in_sizes, int n_in,
                              void* d_out, int out_size)
{
    const float* x    = (const float*)d_in[0];
    const float* maax = (const float*)d_in[1];
    const float* maaw = (const float*)d_in[2];
    const float* maak = (const float*)d_in[3];
    const float* maav = (const float*)d_in[4];
    const float* maar = (const float*)d_in[5];
    const float* maag = (const float*)d_in[6];
    const float* w1   = (const float*)d_in[7];   // [C, 160]
    const float* w2   = (const float*)d_in[8];   // [5, 32, C]
    const float* td   = (const float*)d_in[9];   // [1,1,C]
    const float* dw1  = (const float*)d_in[10];  // [C, 64]
    const float* dw2  = (const float*)d_in[11];  // [64, C]
    const float* u    = (const float*)d_in[12];  // [H, N]
    const float* Wr   = (const float*)d_in[13];
    const float* Wk   = (const float*)d_in[14];
    const float* Wv   = (const float*)d_in[15];
    const float* Wo   = (const float*)d_in[16];
    const float* Wg   = (const float*)d_in[17];
    const float* lnw  = (const float*)d_in[18];
    const float* lnb  = (const float*)d_in[19];
    float* out = (float*)d_out;

    float* xxx = sym_addr(G_XXX);
    float* l1  = sym_addr(G_L1);
    float* m5  = sym_addr(G_M5);
    float* xw  = sym_addr(G_XW);
    float* xk  = sym_addr(G_XK);
    float* xv  = sym_addr(G_XV);
    float* xr  = sym_addr(G_XR);
    float* xg  = sym_addr(G_XG);
    float* d1  = sym_addr(G_D1);
    float* ww  = sym_addr(G_WW);
    float* rr  = sym_addr(G_R);
    float* kk  = sym_addr(G_K);
    float* vv  = sym_addr(G_V);
    float* gl  = sym_addr(G_GL);
    float* ogx = sym_addr(G_OGX);

    const int EW_BLOCKS = (NEL / 4 + 255) / 256;

    // 1. xxx = x + (shift(x)-x)*maa_x
    k_xxx<<<EW_BLOCKS, 256>>>(x, maax);

    // 2. lora1 = tanh(xxx @ w1)   [4096,160] (padded 256)
    gemm_tf32<0><<<dim3(2, 32), 256>>>(xxx, Cc, 0, w1, 160, 0, l1, 256, 0, 160, Cc);
    k_tanh<<<(BT * 256 + 255) / 256, 256>>>(l1, BT * 256);

    // 3. m_f = lora1[:, f] @ w2[f]   (batched over z = 5, K=32)
    gemm_tf32<0><<<dim3(16, 32, 5), 256>>>(l1, 256, 32,
                                           w2, Cc, (size_t)32 * Cc,
                                           m5, Cc, (size_t)NEL, Cc, 32);

    // 4. xw/xk/xv/xr/xg
    k_mix<<<EW_BLOCKS, 256>>>(x, maaw, maak, maav, maar, maag);

    // 5. decay: ww = time_decay + tanh(xw@dw1)@dw2 ; then exp(-exp(ww))
    gemm_tf32<0><<<dim3(1, 32), 256>>>(xw, Cc, 0, dw1, 64, 0, d1, 128, 0, 64, Cc);
    k_tanh<<<(BT * 128 + 255) / 256, 256>>>(d1, BT * 128);
    gemm_tf32<0><<<dim3(16, 32), 256>>>(d1, 128, 0, dw2, Cc, 0, ww, Cc, 0, Cc, 64);
    k_ew<<<EW_BLOCKS, 256>>>(td);

    // 6. projections: r,k,v,g
    gemm_tf32<1><<<dim3(16, 32), 256>>>(xr, Cc, 0, Wr, Cc, 0, rr, Cc, 0, Cc, Cc);
    gemm_tf32<1><<<dim3(16, 32), 256>>>(xk, Cc, 0, Wk, Cc, 0, kk, Cc, 0, Cc, Cc);
    gemm_tf32<1><<<dim3(16, 32), 256>>>(xv, Cc, 0, Wv, Cc, 0, vv, Cc, 0, Cc, Cc);
    gemm_tf32<1><<<dim3(16, 32), 256>>>(xg, Cc, 0, Wg, Cc, 0, gl, Cc, 0, Cc, Cc);

    // 7. WKV recurrence
    k_wkv<<<dim3(2, Hh, Bb), 128>>>(u);

    // 8. GroupNorm * ln + silu(g) gating
    k_gn<<<BT, 256>>>(lnw, lnb);

    // 9. output projection
    gemm_tf32<1><<<dim3(16, 32), 256>>>(ogx, Cc, 0, Wo, Cc, 0, out, Cc, 0, Cc, Cc);

    (void)in_sizes; (void)n_in; (void)out_size;
}

// round 5
// speedup vs baseline: 1.1286x; 1.1286x over previous
#include <cuda_runtime.h>
#include <mma.h>
#include <math.h>
#include <stdint.h>

using namespace nvcuda;

#define Bb 2
#define Tt 2048
#define Cc 2048
#define Hh 32
#define Nn 64
#define BT (Bb*Tt)            /* 4096 */
#define NEL (Bb*Tt*Cc)        /* 8388608 */

// ---------------------------------------------------------------------------
// Scratch (device globals; no dynamic allocation allowed)
// ---------------------------------------------------------------------------
__device__ float G_XXX[NEL];
__device__ float G_L1[BT*256];      // lora1 out (tanh applied), padded 160 -> 256
__device__ float G_M5[5][NEL];      // 5 mix deltas
__device__ float G_XW[NEL];
__device__ float G_XK[NEL];
__device__ float G_XV[NEL];
__device__ float G_XR[NEL];
__device__ float G_XG[NEL];
__device__ float G_D1[BT*128];      // decay lora1 (tanh applied), padded 64 -> 128
__device__ float G_WW[NEL];         // decay -> exp(-exp(w)) in place
__device__ float G_R[NEL];
__device__ float G_K[NEL];
__device__ float G_V[NEL];
__device__ float G_GL[NEL];
__device__ float G_WKV[NEL];
__device__ float G_OGX[NEL];

// ---------------------------------------------------------------------------
// Helpers
// ---------------------------------------------------------------------------
__device__ __forceinline__ uint32_t smem_u32(const void* p) {
    uint32_t a;
    asm("{ .reg .u64 t; cvta.to.shared.u64 t, %1; cvt.u32.u64 %0, t; }"
        : "=r"(a) : "l"(p));
    return a;
}
// cp.async 16B with zero-fill when pred==false (src-size 0)
__device__ __forceinline__ void cpa16(uint32_t dst, const void* src, bool pred) {
    asm volatile("cp.async.cg.shared.global [%0], [%1], 16, %2;"
                 :: "r"(dst), "l"(src), "r"(pred ? 16 : 0) : "memory");
}
#define CP_COMMIT() asm volatile("cp.async.commit_group;" ::: "memory")
#define CP_WAIT0()  asm volatile("cp.async.wait_group 0;" ::: "memory")

// ===========================================================================
// NT GEMM (C = A * W^T), wmma TF32, cp.async double-buffered.
//   A [4096, 2048] row-major, W [2048, 2048] row-major, C [4096, 2048].
//   128x128 tile/CTA, BK=16, 2 stages, 256 threads (4x2 warp grid).
//   Batched over blockIdx.z via pointer table.
// ===========================================================================
struct NTPtrs { const float* A; const float* B; float* C; };
struct NTPtrs4 { NTPtrs s[4]; };

template<int TANH>
__global__ __launch_bounds__(256)
void gemm_nt_cp(NTPtrs4 ps)
{
    constexpr int LDS_ = 20;                 // 16 + 4 pad
    __shared__ __align__(16) float As[2][128 * LDS_];
    __shared__ __align__(16) float Bs[2][128 * LDS_];

    const int tid = threadIdx.x;
    const int wid = tid >> 5;
    const int wm  = wid & 3;                 // 32 M-rows per warp
    const int wn  = wid >> 2;                // 64 N-cols per warp
    const int m0  = blockIdx.y * 128;
    const int n0  = blockIdx.x * 128;
    const float* A  = ps.s[blockIdx.z].A;
    const float* Bm = ps.s[blockIdx.z].B;
    float*       C  = ps.s[blockIdx.z].C;

    const uint32_t asb[2] = { smem_u32(As[0]), smem_u32(As[1]) };
    const uint32_t bsb[2] = { smem_u32(Bs[0]), smem_u32(Bs[1]) };

    const int rowq = tid >> 2;               // 0..63
    const int kq   = tid & 3;                // 16B chunk within 16-float row

    wmma::fragment<wmma::accumulator, 16, 16, 8, float> acc[2][4];
#pragma unroll
    for (int i = 0; i < 2; i++)
#pragma unroll
        for (int j = 0; j < 4; j++)
            wmma::fill_fragment(acc[i][j], 0.0f);

    auto load = [&](int s, int ch) {
        const int kb = ch * 16 + kq * 4;
#pragma unroll
        for (int it = 0; it < 2; it++) {
            int r = rowq + it * 64;
            uint32_t so = (uint32_t)(r * LDS_ + kq * 4) * 4u;
            cpa16(asb[s] + so, A  + (size_t)(m0 + r) * Cc + kb, true);
            cpa16(bsb[s] + so, Bm + (size_t)(n0 + r) * Cc + kb, true);
        }
    };

    auto compute = [&](int s) {
#pragma unroll
        for (int kk = 0; kk < 16; kk += 8) {
            wmma::fragment<wmma::matrix_a, 16, 16, 8, wmma::precision::tf32, wmma::row_major> af[2];
#pragma unroll
            for (int i = 0; i < 2; i++) {
                wmma::load_matrix_sync(af[i], &As[s][(wm * 32 + i * 16) * LDS_ + kk], LDS_);
#pragma unroll
                for (int t = 0; t < af[i].num_elements; t++)
                    af[i].x[t] = wmma::__float_to_tf32(af[i].x[t]);
            }
#pragma unroll
            for (int j = 0; j < 4; j++) {
                wmma::fragment<wmma::matrix_b, 16, 16, 8, wmma::precision::tf32, wmma::col_major> bf;
                wmma::load_matrix_sync(bf, &Bs[s][(wn * 64 + j * 16) * LDS_ + kk], LDS_);
#pragma unroll
                for (int t = 0; t < bf.num_elements; t++)
                    bf.x[t] = wmma::__float_to_tf32(bf.x[t]);
#pragma unroll
                for (int i = 0; i < 2; i++)
                    wmma::mma_sync(acc[i][j], af[i], bf, acc[i][j]);
            }
        }
    };

    const int NCH = Cc / 16;                 // 128
    load(0, 0);
    CP_COMMIT();
    for (int c = 0; c < NCH; c++) {
        CP_WAIT0();
        __syncthreads();                     // stage c visible; compute(c-1) done by all
        int nc = c + 1;
        if (nc < NCH) load(nc & 1, nc);
        CP_COMMIT();
        compute(c & 1);
    }

#pragma unroll
    for (int i = 0; i < 2; i++)
#pragma unroll
        for (int j = 0; j < 4; j++) {
            if (TANH) {
#pragma unroll
                for (int t = 0; t < acc[i][j].num_elements; t++)
                    acc[i][j].x[t] = tanhf(acc[i][j].x[t]);
            }
            wmma::store_matrix_sync(C + (size_t)(m0 + wm * 32 + i * 16) * Cc
                                      + n0 + wn * 64 + j * 16,
                                    acc[i][j], Cc, wmma::mem_row_major);
        }
}

// ===========================================================================
// NN GEMM (C = A * B), wmma TF32, cp.async double-buffered.
//   B [K, N] row-major.  Zero-fill for n >= Nreal.  K multiple of 16.
//   Batched over blockIdx.z with element strides.
// ===========================================================================
template<int TANH>
__global__ __launch_bounds__(256)
void gemm_nn_cp(const float* __restrict__ A, int lda, size_t aB,
                const float* __restrict__ Bm, int ldb, size_t bB,
                float* __restrict__ C, int ldc, size_t cB,
                int Nreal, int Kdim)
{
    constexpr int LDAS = 20;                 // A: 16 + 4 pad
    constexpr int LDBS = 132;                // B: 128 + 4 pad
    __shared__ __align__(16) float As[2][128 * LDAS];
    __shared__ __align__(16) float Bs[2][16 * LDBS];

    A  += (size_t)blockIdx.z * aB;
    Bm += (size_t)blockIdx.z * bB;
    C  += (size_t)blockIdx.z * cB;

    const int tid = threadIdx.x;
    const int wid = tid >> 5;
    const int wm  = wid & 3;
    const int wn  = wid >> 2;
    const int m0  = blockIdx.y * 128;
    const int n0  = blockIdx.x * 128;

    const uint32_t asb[2] = { smem_u32(As[0]), smem_u32(As[1]) };
    const uint32_t bsb[2] = { smem_u32(Bs[0]), smem_u32(Bs[1]) };

    const int rowa = tid >> 2, kqa = tid & 3;    // A staging
    const int rowb = tid >> 5, nqb = tid & 31;   // B staging

    wmma::fragment<wmma::accumulator, 16, 16, 8, float> acc[2][4];
#pragma unroll
    for (int i = 0; i < 2; i++)
#pragma unroll
        for (int j = 0; j < 4; j++)
            wmma::fill_fragment(acc[i][j], 0.0f);

    auto load = [&](int s, int ch) {
#pragma unroll
        for (int it = 0; it < 2; it++) {
            int ra = rowa + it * 64;
            cpa16(asb[s] + (uint32_t)(ra * LDAS + kqa * 4) * 4u,
                  A + (size_t)(m0 + ra) * lda + ch * 16 + kqa * 4, true);
            int rb = rowb + it * 8;
            cpa16(bsb[s] + (uint32_t)(rb * LDBS + nqb * 4) * 4u,
                  Bm + (size_t)(ch * 16 + rb) * ldb + n0 + nqb * 4,
                  n0 + nqb * 4 < Nreal);
        }
    };

    auto compute = [&](int s) {
#pragma unroll
        for (int kk = 0; kk < 16; kk += 8) {
            wmma::fragment<wmma::matrix_a, 16, 16, 8, wmma::precision::tf32, wmma::row_major> af[2];
#pragma unroll
            for (int i = 0; i < 2; i++) {
                wmma::load_matrix_sync(af[i], &As[s][(wm * 32 + i * 16) * LDAS + kk], LDAS);
#pragma unroll
                for (int t = 0; t < af[i].num_elements; t++)
                    af[i].x[t] = wmma::__float_to_tf32(af[i].x[t]);
            }
#pragma unroll
            for (int j = 0; j < 4; j++) {
                wmma::fragment<wmma::matrix_b, 16, 16, 8, wmma::precision::tf32, wmma::row_major> bf;
                wmma::load_matrix_sync(bf, &Bs[s][kk * LDBS + wn * 64 + j * 16], LDBS);
#pragma unroll
                for (int t = 0; t < bf.num_elements; t++)
                    bf.x[t] = wmma::__float_to_tf32(bf.x[t]);
#pragma unroll
                for (int i = 0; i < 2; i++)
                    wmma::mma_sync(acc[i][j], af[i], bf, acc[i][j]);
            }
        }
    };

    const int NCH = Kdim / 16;
    load(0, 0);
    CP_COMMIT();
    for (int c = 0; c < NCH; c++) {
        CP_WAIT0();
        __syncthreads();
        int nc = c + 1;
        if (nc < NCH) load(nc & 1, nc);
        CP_COMMIT();
        compute(c & 1);
    }

#pragma unroll
    for (int i = 0; i < 2; i++)
#pragma unroll
        for (int j = 0; j < 4; j++) {
            if (TANH) {
#pragma unroll
                for (int t = 0; t < acc[i][j].num_elements; t++)
                    acc[i][j].x[t] = tanhf(acc[i][j].x[t]);
            }
            wmma::store_matrix_sync(C + (size_t)(m0 + wm * 32 + i * 16) * ldc
                                      + n0 + wn * 64 + j * 16,
                                    acc[i][j], ldc, wmma::mem_row_major);
        }
}

// ---------------------------------------------------------------------------
// Elementwise kernels (float4 over NEL; Cc/4 = 512, Tt = 2048 — powers of 2)
// ---------------------------------------------------------------------------
__global__ void k_xxx(const float* __restrict__ x, const float* __restrict__ maa_x)
{
    int i = blockIdx.x * blockDim.x + threadIdx.x;
    if (i >= NEL / 4) return;
    int c4 = i & 511;
    int bt = i >> 9;
    int t  = bt & (Tt - 1);
    float4 xv = ((const float4*)x)[i];
    float4 xp = make_float4(0.f, 0.f, 0.f, 0.f);
    if (t > 0) xp = ((const float4*)x)[i - 512];
    float4 mm = ((const float4*)maa_x)[c4];
    float4 o;
    o.x = xv.x + (xp.x - xv.x) * mm.x;
    o.y = xv.y + (xp.y - xv.y) * mm.y;
    o.z = xv.z + (xp.z - xv.z) * mm.z;
    o.w = xv.w + (xp.w - xv.w) * mm.w;
    ((float4*)G_XXX)[i] = o;
}

__global__ void k_mix(const float* __restrict__ x,
                      const float* __restrict__ maw, const float* __restrict__ mak,
                      const float* __restrict__ mav, const float* __restrict__ mar,
                      const float* __restrict__ mag)
{
    int i = blockIdx.x * blockDim.x + threadIdx.x;
    if (i >= NEL / 4) return;
    int c4 = i & 511;
    int bt = i >> 9;
    int t  = bt & (Tt - 1);
    float4 xv = ((const float4*)x)[i];
    float4 xp = make_float4(0.f, 0.f, 0.f, 0.f);
    if (t > 0) xp = ((const float4*)x)[i - 512];
    float4 xx;
    xx.x = xp.x - xv.x; xx.y = xp.y - xv.y; xx.z = xp.z - xv.z; xx.w = xp.w - xv.w;

#define MIX_ONE(MAA, FIDX, DST)                                              \
    {                                                                        \
        float4 ma = ((const float4*)(MAA))[c4];                              \
        float4 md = ((const float4*)(G_M5[FIDX]))[i];                        \
        float4 o;                                                            \
        o.x = xv.x + xx.x * (ma.x + md.x);                                   \
        o.y = xv.y + xx.y * (ma.y + md.y);                                   \
        o.z = xv.z + xx.z * (ma.z + md.z);                                   \
        o.w = xv.w + xx.w * (ma.w + md.w);                                   \
        ((float4*)(DST))[i] = o;                                             \
    }
    MIX_ONE(maw, 0, G_XW)
    MIX_ONE(mak, 1, G_XK)
    MIX_ONE(mav, 2, G_XV)
    MIX_ONE(mar, 3, G_XR)
    MIX_ONE(mag, 4, G_XG)
#undef MIX_ONE
}

__global__ void k_ew(const float* __restrict__ td)
{
    int i = blockIdx.x * blockDim.x + threadIdx.x;
    if (i >= NEL / 4) return;
    int c4 = i & 511;
    float4 wv = ((float4*)G_WW)[i];
    float4 tv = ((const float4*)td)[c4];
    wv.x = expf(-expf(tv.x + wv.x));
    wv.y = expf(-expf(tv.y + wv.y));
    wv.z = expf(-expf(tv.z + wv.z));
    wv.w = expf(-expf(tv.w + wv.w));
    ((float4*)G_WW)[i] = wv;
}

// ---------------------------------------------------------------------------
// WKV6 recurrence.  grid (2, H, B): vsplit, head, batch.  128 threads:
// thread = (vcol 0..31, kquarter 0..3); 16 state elements per thread.
// ---------------------------------------------------------------------------
__global__ __launch_bounds__(128)
void k_wkv(const float* __restrict__ U)
{
    __shared__ __align__(16) float sr[64];
    __shared__ __align__(16) float sk[64];
    __shared__ __align__(16) float sew[64];
    __shared__ __align__(16) float sv[32];
    __shared__ float sacc[128];

    const int tid  = threadIdx.x;
    const int vs   = blockIdx.x;
    const int h    = blockIdx.y;
    const int b    = blockIdx.z;
    const int vloc = tid & 31;
    const int kq   = tid >> 5;
    const int k0   = kq * 16;

    float u[16], s[16];
#pragma unroll
    for (int i = 0; i < 16; i++) {
        u[i] = U[h * 64 + k0 + i];
        s[i] = 0.f;
    }

    size_t base = (size_t)b * Tt * Cc + (size_t)h * 64;
    for (int t = 0; t < Tt; t++, base += Cc) {
        if (tid < 64) {
            sr[tid]  = G_R[base + tid];
            sew[tid] = G_WW[base + tid];
        } else {
            int j = tid - 64;
            sk[j] = G_K[base + j];
            if (j < 32) sv[j] = G_V[base + vs * 32 + j];
        }
        __syncthreads();

        const float vj = sv[vloc];
        float acc = 0.f;
        const float4* r4 = (const float4*)(sr + k0);
        const float4* c4 = (const float4*)(sk + k0);
        const float4* e4 = (const float4*)(sew + k0);
#pragma unroll
        for (int qq = 0; qq < 4; qq++) {
            float4 rr = r4[qq], kk = c4[qq], ee = e4[qq];
            float p;
            p = kk.x * vj; acc = fmaf(rr.x, fmaf(u[qq*4+0], p, s[qq*4+0]), acc); s[qq*4+0] = fmaf(ee.x, s[qq*4+0], p);
            p = kk.y * vj; acc = fmaf(rr.y, fmaf(u[qq*4+1], p, s[qq*4+1]), acc); s[qq*4+1] = fmaf(ee.y, s[qq*4+1], p);
            p = kk.z * vj; acc = fmaf(rr.z, fmaf(u[qq*4+2], p, s[qq*4+2]), acc); s[qq*4+2] = fmaf(ee.z, s[qq*4+2], p);
            p = kk.w * vj; acc = fmaf(rr.w, fmaf(u[qq*4+3], p, s[qq*4+3]), acc); s[qq*4+3] = fmaf(ee.w, s[qq*4+3], p);
        }
        sacc[tid] = acc;
        __syncthreads();
        if (tid < 32)
            G_WKV[base + vs * 32 + tid] =
                sacc[tid] + sacc[tid + 32] + sacc[tid + 64] + sacc[tid + 96];
    }
}

// ---------------------------------------------------------------------------
// GroupNorm(per head) * ln_w + ln_b, then * silu(g).  One block per token.
// ---------------------------------------------------------------------------
__global__ __launch_bounds__(256)
void k_gn(const float* __restrict__ lnw, const float* __restrict__ lnb)
{
    const int token = blockIdx.x;
    const int lane  = threadIdx.x & 31;
    const int w     = threadIdx.x >> 5;
    const size_t tbase = (size_t)token * Cc;
#pragma unroll
    for (int hh = 0; hh < 4; hh++) {
        int h = w * 4 + hh;
        size_t base = tbase + (size_t)h * 64;
        float e0 = G_WKV[base + lane];
        float e1 = G_WKV[base + 32 + lane];
        float sum = e0 + e1;
#pragma unroll
        for (int o = 16; o > 0; o >>= 1) sum += __shfl_xor_sync(0xffffffffu, sum, o);
        float mean = sum * (1.f / 64.f);
        float d0 = e0 - mean, d1 = e1 - mean;
        float vr = d0 * d0 + d1 * d1;
#pragma unroll
        for (int o = 16; o > 0; o >>= 1) vr += __shfl_xor_sync(0xffffffffu, vr, o);
        float inv = rsqrtf(vr * (1.f / 64.f) + 6.4e-4f);   // EPS = 1e-5 * 8^2
        int c0 = h * 64 + lane, c1 = c0 + 32;
        float g0 = G_GL[base + lane];
        float g1 = G_GL[base + 32 + lane];
        g0 = g0 / (1.f + expf(-g0));
        g1 = g1 / (1.f + expf(-g1));
        G_OGX[base + lane]      = (d0 * inv * lnw[c0] + lnb[c0]) * g0;
        G_OGX[base + 32 + lane] = (d1 * inv * lnw[c1] + lnb[c1]) * g1;
    }
}

// ---------------------------------------------------------------------------
// Host launch
// ---------------------------------------------------------------------------
static float* sym_addr(const void* symbol)
{
    void* p = nullptr;
    cudaGetSymbolAddress(&p, symbol);
    return (float*)p;
}

extern "C" void kernel_launch(void* const* d_in, const int* in_sizes, int n_in,
                              void* d_out, int out_size)
{
    const float* x    = (const float*)d_in[0];
    const float* maax = (const float*)d_in[1];
    const float* maaw = (const float*)d_in[2];
    const float* maak = (const float*)d_in[3];
    const float* maav = (const float*)d_in[4];
    const float* maar = (const float*)d_in[5];
    const float* maag = (const float*)d_in[6];
    const float* w1   = (const float*)d_in[7];   // [C, 160]
    const float* w2   = (const float*)d_in[8];   // [5, 32, C]
    const float* td   = (const float*)d_in[9];   // [1,1,C]
    const float* dw1  = (const float*)d_in[10];  // [C, 64]
    const float* dw2  = (const float*)d_in[11];  // [64, C]
    const float* u    = (const float*)d_in[12];  // [H, N]
    const float* Wr   = (const float*)d_in[13];
    const float* Wk   = (const float*)d_in[14];
    const float* Wv   = (const float*)d_in[15];
    const float* Wo   = (const float*)d_in[16];
    const float* Wg   = (const float*)d_in[17];
    const float* lnw  = (const float*)d_in[18];
    const float* lnb  = (const float*)d_in[19];
    float* out = (float*)d_out;

    float* xxx = sym_addr(G_XXX);
    float* l1  = sym_addr(G_L1);
    float* m5  = sym_addr(G_M5);
    float* xw  = sym_addr(G_XW);
    float* xk  = sym_addr(G_XK);
    float* xv  = sym_addr(G_XV);
    float* xr  = sym_addr(G_XR);
    float* xg  = sym_addr(G_XG);
    float* d1  = sym_addr(G_D1);
    float* ww  = sym_addr(G_WW);
    float* rr  = sym_addr(G_R);
    float* kk  = sym_addr(G_K);
    float* vv  = sym_addr(G_V);
    float* gl  = sym_addr(G_GL);
    float* ogx = sym_addr(G_OGX);

    const int EW_BLOCKS = (NEL / 4 + 255) / 256;

    // 1. xxx = x + (shift(x)-x)*maa_x
    k_xxx<<<EW_BLOCKS, 256>>>(x, maax);

    // 2. lora1 = tanh(xxx @ w1)   [4096,160] (padded 256), tanh fused
    gemm_nn_cp<1><<<dim3(2, 32), 256>>>(xxx, Cc, 0, w1, 160, 0,
                                        l1, 256, 0, 160, Cc);

    // 3. m_f = lora1[:, f] @ w2[f]   (batched over z = 5, K=32)
    gemm_nn_cp<0><<<dim3(16, 32, 5), 256>>>(l1, 256, 32,
                                            w2, Cc, (size_t)32 * Cc,
                                            m5, Cc, (size_t)NEL, Cc, 32);

    // 4. xw/xk/xv/xr/xg
    k_mix<<<EW_BLOCKS, 256>>>(x, maaw, maak, maav, maar, maag);

    // 5. decay lora1 = tanh(xw @ dw1)   [4096,64] (padded 128), tanh fused
    gemm_nn_cp<1><<<dim3(1, 32), 256>>>(xw, Cc, 0, dw1, 64, 0,
                                        d1, 128, 0, 64, Cc);

    // 6. projections r,k,v,g  (launch #6 -> ncu profiles this)
    {
        NTPtrs4 ps;
        ps.s[0] = {xr, Wr, rr};
        ps.s[1] = {xk, Wk, kk};
        ps.s[2] = {xv, Wv, vv};
        ps.s[3] = {xg, Wg, gl};
        gemm_nt_cp<0><<<dim3(16, 32, 4), 256>>>(ps);
    }

    // 7. ww_pre = d1 @ dw2 ; then 8. exp(-exp(time_decay + ww_pre))
    gemm_nn_cp<0><<<dim3(16, 32), 256>>>(d1, 128, 0, dw2, Cc, 0,
                                         ww, Cc, 0, Cc, 64);
    k_ew<<<EW_BLOCKS, 256>>>(td);

    // 9. WKV recurrence
    k_wkv<<<dim3(2, Hh, Bb), 128>>>(u);

    // 10. GroupNorm * ln + silu(g) gating
    k_gn<<<BT, 256>>>(lnw, lnb);

    // 11. output projection
    {
        NTPtrs4 ps;
        ps.s[0] = {ogx, Wo, out};
        ps.s[1] = {ogx, Wo, out};
        ps.s[2] = {ogx, Wo, out};
        ps.s[3] = {ogx, Wo, out};
        gemm_nt_cp<0><<<dim3(16, 32, 1), 256>>>(ps);
    }

    (void)in_sizes; (void)n_in; (void)out_size;
}